// round 12
// baseline (speedup 1.0000x reference)
#include <cuda_runtime.h>
#include <cstdint>

#define NN 30000      // nodes per type
#define NE 100000     // edges per type
#define NT 6          // edge types
#define DI 128        // raw input dim
#define FF 256        // H*C
#define HH 8
#define CC 32

// ---------------- device scratch (static, no allocation) ----------------
__device__ float g_hs[(size_t)NN * FF];      // src-projected features (current layer)
__device__ float g_hd[(size_t)NN * FF];      // dst-projected features (current layer)
__device__ float g_x1[(size_t)NN * FF];      // layer-1 output after LN+ReLU
__device__ float g_es[(size_t)NN * HH];
__device__ float g_ed[(size_t)NN * HH];
__device__ int   g_cnt[NN];
__device__ int   g_row[NN + 1];
__device__ int   g_next[NN];
__device__ int   g_eid[NE];
__device__ float g_pooled[NT * FF + DI];     // [6*256 pooled x2 | 128 x_pkg mean]
__device__ float g_alpha_fallback[(size_t)NE * HH];  // used only if out_size unexpected

// ---------------- tiny utility kernels ----------------
__global__ void k_zero_pooled() {
    int i = blockIdx.x * blockDim.x + threadIdx.x;
    if (i < NT * FF + DI) g_pooled[i] = 0.0f;
}
__global__ void k_zero_cnt() {
    int i = blockIdx.x * blockDim.x + threadIdx.x;
    if (i < NN) g_cnt[i] = 0;
}

__global__ void k_pkg_mean(const float* __restrict__ x_pkg) {
    // grid 100 blocks x 128 threads; block b handles rows [b*300, b*300+300)
    int t = threadIdx.x;
    int r0 = blockIdx.x * 300;
    float s = 0.0f;
    for (int r = r0; r < r0 + 300; r++) s += x_pkg[(size_t)r * DI + t];
    atomicAdd(&g_pooled[NT * FF + t], s * (1.0f / NN));
}

// ---------------- CSR construction ----------------
__global__ void k_hist(const int* __restrict__ dst) {
    int i = blockIdx.x * blockDim.x + threadIdx.x;
    if (i < NE) atomicAdd(&g_cnt[dst[i]], 1);
}

__global__ void k_scan() {
    // single block, 1024 threads, chunk=30 (covers 30720 >= 30000)
    __shared__ int sm[1024];
    const int CH = 30;
    int t = threadIdx.x;
    int base = t * CH;
    int s = 0;
    for (int i = 0; i < CH; i++) {
        int idx = base + i;
        if (idx < NN) s += g_cnt[idx];
    }
    sm[t] = s;
    __syncthreads();
    for (int off = 1; off < 1024; off <<= 1) {
        int v = (t >= off) ? sm[t - off] : 0;
        __syncthreads();
        sm[t] += v;
        __syncthreads();
    }
    int run = (t == 0) ? 0 : sm[t - 1];
    for (int i = 0; i < CH; i++) {
        int idx = base + i;
        if (idx < NN) {
            g_row[idx] = run;
            g_next[idx] = run;
            run += g_cnt[idx];
        }
    }
    if (t == 1023) g_row[NN] = sm[1023];
}

__global__ void k_scatter(const int* __restrict__ dst) {
    int i = blockIdx.x * blockDim.x + threadIdx.x;
    if (i < NE) {
        int d = dst[i];
        int p = atomicAdd(&g_next[d], 1);
        g_eid[p] = i;
    }
}

// ---------------- SGEMM: C[30000,256] = A[30000,K] @ B[K,256], fp32 via FFMA2 ----------------
// cdst: 0 -> g_hs, 1 -> g_hd.  A_==nullptr -> use g_x1 as A.
__global__ __launch_bounds__(256, 2) void sgemm_kernel(const float* A_,
                                                       const float* __restrict__ B,
                                                       int K, int cdst) {
    const float* A = A_ ? A_ : g_x1;
    float* C = cdst ? g_hd : g_hs;
    const int M = NN;

    __shared__ float As[16][128];
    __shared__ float Bs[16][128];

    int tid = threadIdx.x;
    int tx = tid & 15;          // 0..15 -> 8 cols each
    int ty = tid >> 4;          // 0..15 -> 8 rows each
    int row0 = blockIdx.x * 128;
    int col0 = blockIdx.y * 128;

    unsigned long long acc[8][4];
#pragma unroll
    for (int i = 0; i < 8; i++)
#pragma unroll
        for (int j = 0; j < 4; j++) acc[i][j] = 0ULL;

    for (int k0 = 0; k0 < K; k0 += 16) {
        // A tile: 128 rows x 16 cols (store transposed: As[col][row])
#pragma unroll
        for (int i = 0; i < 2; i++) {
            int idx = tid + i * 256;       // 0..511
            int r = idx >> 2;              // 0..127
            int c4 = (idx & 3) * 4;        // 0,4,8,12
            int gr = row0 + r;
            float4 v = make_float4(0.f, 0.f, 0.f, 0.f);
            if (gr < M) v = *(const float4*)(A + (size_t)gr * K + k0 + c4);
            As[c4 + 0][r] = v.x; As[c4 + 1][r] = v.y;
            As[c4 + 2][r] = v.z; As[c4 + 3][r] = v.w;
        }
        // B tile: 16 rows x 128 cols
#pragma unroll
        for (int i = 0; i < 2; i++) {
            int idx = tid + i * 256;
            int r = idx >> 5;              // 0..15
            int c4 = (idx & 31) * 4;       // 0..124
            float4 v = *(const float4*)(B + (size_t)(k0 + r) * FF + col0 + c4);
            *(float4*)&Bs[r][c4] = v;
        }
        __syncthreads();
#pragma unroll
        for (int k = 0; k < 16; k++) {
            unsigned long long a2[8], b2[4];
#pragma unroll
            for (int j = 0; j < 4; j++)
                b2[j] = *(const unsigned long long*)&Bs[k][tx * 8 + j * 2];
#pragma unroll
            for (int i = 0; i < 8; i++) {
                float a = As[k][ty * 8 + i];
                asm("mov.b64 %0, {%1, %1};" : "=l"(a2[i]) : "f"(a));
            }
#pragma unroll
            for (int i = 0; i < 8; i++)
#pragma unroll
                for (int j = 0; j < 4; j++)
                    asm("fma.rn.f32x2 %0, %1, %2, %0;"
                        : "+l"(acc[i][j]) : "l"(a2[i]), "l"(b2[j]));
        }
        __syncthreads();
    }

#pragma unroll
    for (int i = 0; i < 8; i++) {
        int gr = row0 + ty * 8 + i;
        if (gr < M) {
            float o[8];
#pragma unroll
            for (int j = 0; j < 4; j++)
                asm("mov.b64 {%0, %1}, %2;" : "=f"(o[2 * j]), "=f"(o[2 * j + 1]) : "l"(acc[i][j]));
            float* cp = C + (size_t)gr * FF + col0 + tx * 8;
            *(float4*)cp = make_float4(o[0], o[1], o[2], o[3]);
            *(float4*)(cp + 4) = make_float4(o[4], o[5], o[6], o[7]);
        }
    }
}

// ---------------- attention-logit dot products: es/ed from hs/hd ----------------
__global__ void k_dots(const float* __restrict__ as, const float* __restrict__ ad) {
    int i = blockIdx.x * blockDim.x + threadIdx.x;   // over NN*HH
    if (i >= NN * HH) return;
    int n = i >> 3;
    int h = i & 7;
    const float* hsp = g_hs + (size_t)n * FF + h * CC;
    const float* hdp = g_hd + (size_t)n * FF + h * CC;
    const float* ap = as + h * CC;
    const float* bp = ad + h * CC;
    float s1 = 0.f, s2 = 0.f;
#pragma unroll
    for (int c = 0; c < CC; c++) {
        s1 = fmaf(hsp[c], ap[c], s1);
        s2 = fmaf(hdp[c], bp[c], s2);
    }
    g_es[i] = s1;
    g_ed[i] = s2;
}

// ---------------- warp-per-dst segment softmax + aggregation + LN/ReLU ----------------
// POOL=false: write x1;  POOL=true: accumulate mean-pool into g_pooled[t*256 + c]
template <bool POOL>
__global__ __launch_bounds__(256) void k_edge(const int* __restrict__ src,
                                              const float* __restrict__ bias,
                                              const float* __restrict__ gamma,
                                              const float* __restrict__ beta,
                                              float* __restrict__ alpha,
                                              int t) {
    __shared__ float pool_acc[FF];
    if (POOL) {
        pool_acc[threadIdx.x] = 0.0f;
        __syncthreads();
    }

    int d = (blockIdx.x * blockDim.x + threadIdx.x) >> 5;   // grid sized so d < NN always
    int lane = threadIdx.x & 31;
    int h = lane & 7;

    int r0 = g_row[d], r1 = g_row[d + 1];
    float edv = g_ed[(size_t)d * HH + h];

    // pass 1: per-head max
    float m = -3.0e38f;
    for (int j = r0; j < r1; j++) {
        int e = g_eid[j];
        int s = src[e];
        float v = g_es[(size_t)s * HH + h] + edv;
        v = (v > 0.f) ? v : 0.2f * v;
        m = fmaxf(m, v);
    }
    // pass 2: exp-sum; store unnormalized exp to alpha buffer
    float den = 0.f;
    for (int j = r0; j < r1; j++) {
        int e = g_eid[j];
        int s = src[e];
        float v = g_es[(size_t)s * HH + h] + edv;
        v = (v > 0.f) ? v : 0.2f * v;
        float ex = __expf(v - m);
        den += ex;
        if (lane < 8) alpha[(size_t)e * HH + h] = ex;
    }
    float inv = 1.0f / (den + 1e-16f);

    // pass 3: normalize alpha, gather hs[src] and accumulate
    float acc[HH];
#pragma unroll
    for (int k = 0; k < HH; k++) acc[k] = 0.f;

    for (int j = r0; j < r1; j++) {
        int e = g_eid[j];
        int s = src[e];
        float a_h = 0.f;
        if (lane < 8) {
            a_h = alpha[(size_t)e * HH + h] * inv;
            alpha[(size_t)e * HH + h] = a_h;
        }
        float av[HH];
#pragma unroll
        for (int k = 0; k < HH; k++) av[k] = __shfl_sync(0xffffffffu, a_h, k);
        const float* hsp = g_hs + (size_t)s * FF + lane;
#pragma unroll
        for (int k = 0; k < HH; k++) acc[k] = fmaf(av[k], hsp[k * CC], acc[k]);
    }

    // epilogue: +bias, LayerNorm over 256 (warp-held), ReLU
    float y[HH];
    float s1 = 0.f, s2 = 0.f;
#pragma unroll
    for (int k = 0; k < HH; k++) {
        float x = acc[k] + bias[k * CC + lane];
        y[k] = x;
        s1 += x;
        s2 = fmaf(x, x, s2);
    }
#pragma unroll
    for (int off = 16; off > 0; off >>= 1) {
        s1 += __shfl_xor_sync(0xffffffffu, s1, off);
        s2 += __shfl_xor_sync(0xffffffffu, s2, off);
    }
    float mu = s1 * (1.0f / FF);
    float var = s2 * (1.0f / FF) - mu * mu;
    float rstd = rsqrtf(var + 1e-5f);
#pragma unroll
    for (int k = 0; k < HH; k++) {
        int c = k * CC + lane;
        float v = fmaf((y[k] - mu) * rstd, gamma[c], beta[c]);
        v = fmaxf(v, 0.0f);
        if (POOL) atomicAdd(&pool_acc[c], v);
        else g_x1[(size_t)d * FF + c] = v;
    }

    if (POOL) {
        __syncthreads();
        atomicAdd(&g_pooled[t * FF + threadIdx.x], pool_acc[threadIdx.x] * (1.0f / NN));
    }
}

// ---------------- final classifier dot ----------------
__global__ void k_final(const float* __restrict__ Wc, const float* __restrict__ bc,
                        float* __restrict__ out) {
    __shared__ float sm[256];
    int tid = threadIdx.x;
    float s = 0.f;
    for (int i = tid; i < NT * FF + DI; i += 256) s = fmaf(g_pooled[i], Wc[i], s);
    sm[tid] = s;
    __syncthreads();
    for (int off = 128; off > 0; off >>= 1) {
        if (tid < off) sm[tid] += sm[tid + off];
        __syncthreads();
    }
    if (tid == 0) out[0] = sm[0] + bc[0];
}

// ---------------- launch ----------------
extern "C" void kernel_launch(void* const* d_in, const int* in_sizes, int n_in,
                              void* d_out, int out_size) {
    const float* x_pkg = (const float*)d_in[0];
    const float* x_tgt = (const float*)d_in[1];
    const int*   ei    = (const int*)d_in[2];
    const float* W1s   = (const float*)d_in[3];
    const float* W1d   = (const float*)d_in[4];
    const float* a1s   = (const float*)d_in[5];
    const float* a1d   = (const float*)d_in[6];
    const float* b1    = (const float*)d_in[7];
    const float* W2s   = (const float*)d_in[8];
    const float* W2d   = (const float*)d_in[9];
    const float* a2s   = (const float*)d_in[10];
    const float* a2d   = (const float*)d_in[11];
    const float* b2    = (const float*)d_in[12];
    const float* gamma = (const float*)d_in[13];
    const float* beta  = (const float*)d_in[14];
    const float* Wc    = (const float*)d_in[15];
    const float* bc    = (const float*)d_in[16];
    float* out = (float*)d_out;

    // alpha2 output region: logits at out[0], alpha2 [6,100000,8] after it.
    const bool alpha_fits = (out_size >= 1 + NT * NE * HH);

    k_zero_pooled<<<7, 256>>>();
    k_pkg_mean<<<100, 128>>>(x_pkg);

    dim3 gg(235, 2);
    for (int t = 0; t < NT; t++) {
        const int* src = ei + (size_t)t * 2 * NE;
        const int* dst = src + NE;
        float* alpha = alpha_fits ? (out + 1 + (size_t)t * NE * HH) : g_alpha_fallback;

        // CSR by dst (shared by both layers)
        k_zero_cnt<<<118, 256>>>();
        k_hist<<<391, 256>>>(dst);
        k_scan<<<1, 1024>>>();
        k_scatter<<<391, 256>>>(dst);

        // ---- layer 1 ----
        sgemm_kernel<<<gg, 256>>>(x_pkg, W1s + (size_t)t * DI * FF, DI, 0);
        sgemm_kernel<<<gg, 256>>>(x_tgt + (size_t)t * NN * DI,
                                  W1d + (size_t)t * DI * FF, DI, 1);
        k_dots<<<938, 256>>>(a1s + t * FF, a1d + t * FF);
        k_edge<false><<<3750, 256>>>(src, b1 + t * FF, gamma + t * FF, beta + t * FF,
                                     alpha, t);

        // ---- layer 2 ----
        sgemm_kernel<<<gg, 256>>>(x_pkg, W2s + (size_t)t * DI * FF, DI, 0);
        sgemm_kernel<<<gg, 256>>>(nullptr /*g_x1*/, W2d + (size_t)t * FF * FF, FF, 1);
        k_dots<<<938, 256>>>(a2s + t * FF, a2d + t * FF);
        k_edge<true><<<3750, 256>>>(src, b2 + t * FF, gamma + t * FF, beta + t * FF,
                                    alpha, t);
    }

    k_final<<<1, 256>>>(Wc, bc, out);
}

// round 13
// speedup vs baseline: 1.6778x; 1.6778x over previous
#include <cuda_runtime.h>
#include <cstdint>

#define NN 30000      // nodes per type
#define NE 100000     // edges per type
#define NT 6          // edge types
#define DI 128        // raw input dim
#define FF 256        // H*C
#define HH 8
#define CC 32

// ---------------- device scratch (static, no allocation) ----------------
__device__ float g_hs[(size_t)NT * NN * FF];   // src-projected features per type
__device__ float g_x1[(size_t)NT * NN * FF];   // layer-1 output per type
__device__ float g_es[(size_t)NT * NN * HH];
__device__ float g_ed[(size_t)NT * NN * HH];
__device__ int   g_cnt[NT][NN];
__device__ int   g_row[NT][NN + 1];
__device__ int   g_next[NT][NN];
__device__ int   g_eid[NT][NE];
__device__ float g_pooled[NT * FF + DI];
__device__ float g_alpha_fb[(size_t)NE * HH];  // sink if out_size unexpected

// ---------------- tiny utility kernels ----------------
__global__ void k_zero_pooled() {
    int i = blockIdx.x * blockDim.x + threadIdx.x;
    if (i < NT * FF + DI) g_pooled[i] = 0.0f;
}
__global__ void k_zero_cnt() {
    int i = blockIdx.x * blockDim.x + threadIdx.x;
    if (i < NT * NN) ((int*)g_cnt)[i] = 0;
}
__global__ void k_pkg_mean(const float* __restrict__ x_pkg) {
    int t = threadIdx.x;
    int r0 = blockIdx.x * 300;
    float s = 0.0f;
    for (int r = r0; r < r0 + 300; r++) s += x_pkg[(size_t)r * DI + t];
    atomicAdd(&g_pooled[NT * FF + t], s * (1.0f / NN));
}

// ---------------- CSR construction (batched over types) ----------------
__global__ void k_hist(const int* __restrict__ ei) {
    int t = blockIdx.y;
    const int* dst = ei + (size_t)t * 2 * NE + NE;
    int i = blockIdx.x * blockDim.x + threadIdx.x;
    if (i < NE) atomicAdd(&g_cnt[t][dst[i]], 1);
}

__global__ void k_scan() {
    __shared__ int sm[1024];
    const int CH = 30;
    int t = blockIdx.x;
    int tt = threadIdx.x;
    int base = tt * CH;
    int s = 0;
    for (int i = 0; i < CH; i++) {
        int idx = base + i;
        if (idx < NN) s += g_cnt[t][idx];
    }
    sm[tt] = s;
    __syncthreads();
    for (int off = 1; off < 1024; off <<= 1) {
        int v = (tt >= off) ? sm[tt - off] : 0;
        __syncthreads();
        sm[tt] += v;
        __syncthreads();
    }
    int run = (tt == 0) ? 0 : sm[tt - 1];
    for (int i = 0; i < CH; i++) {
        int idx = base + i;
        if (idx < NN) {
            g_row[t][idx] = run;
            g_next[t][idx] = run;
            run += g_cnt[t][idx];
        }
    }
    if (tt == 1023) g_row[t][NN] = sm[1023];
}

__global__ void k_scatter(const int* __restrict__ ei) {
    int t = blockIdx.y;
    const int* dst = ei + (size_t)t * 2 * NE + NE;
    int i = blockIdx.x * blockDim.x + threadIdx.x;
    if (i < NE) {
        int d = dst[i];
        int p = atomicAdd(&g_next[t][d], 1);
        g_eid[t][p] = i;
    }
}

// ---------------- batched SGEMM + fused attention-dot epilogue ----------------
// z < NT : src GEMM  t=z      : C = A_src @ Ws[t]  -> g_hs[t], es[t] fused
// z >= NT: dst GEMM  t=z-NT   : (A_dst[t] @ Wd[t]) -> ed[t] only (hd never stored)
// Adst == nullptr -> use g_x1 as the dst-side A (layer 2), stride NN*Kd.
__global__ __launch_bounds__(256, 2) void k_gemm(
    const float* __restrict__ x_pkg,
    const float* Adst,
    const float* __restrict__ Ws,
    const float* __restrict__ Wd,
    const float* __restrict__ atts,
    const float* __restrict__ attd,
    int Kd)
{
    __shared__ float As[2][16][256];   // duplicated A: As[k][2m]==As[k][2m+1]
    __shared__ float Bs[2][16][128];

    int z = blockIdx.z;
    int is_d = (z >= NT);
    int t = is_d ? z - NT : z;
    const float* A;
    const float* B;
    float* C;
    const float* att;
    float* eo;
    int K;
    if (!is_d) {
        A = x_pkg; K = DI;
        B = Ws + (size_t)t * DI * FF;
        C = g_hs + (size_t)t * NN * FF;
        att = atts + t * FF;
        eo = g_es + (size_t)t * NN * HH;
    } else {
        const float* Ab = Adst ? Adst : g_x1;
        K = Kd;
        A = Ab + (size_t)t * NN * K;
        B = Wd + (size_t)t * K * FF;
        C = nullptr;
        att = attd + t * FF;
        eo = g_ed + (size_t)t * NN * HH;
    }

    int tid = threadIdx.x;
    int tx = tid & 15;
    int ty = tid >> 4;
    int row0 = blockIdx.x * 128;
    int col0 = blockIdx.y * 128;
    int nk = K >> 4;

    // per-thread fixed load coordinates
    const int ar0 = tid >> 2, ac = (tid & 3) * 4;      // A rows ar0, ar0+64
    const int br0 = tid >> 5, bc = (tid & 31) * 4;     // B rows br0, br0+8

    float4 pa0, pa1, pb0, pb1;

    unsigned long long acc[8][4];
#pragma unroll
    for (int i = 0; i < 8; i++)
#pragma unroll
        for (int j = 0; j < 4; j++) acc[i][j] = 0ULL;

#define G2R(K0)                                                               \
    {                                                                         \
        int gr0 = row0 + ar0, gr1 = row0 + ar0 + 64;                          \
        pa0 = make_float4(0.f, 0.f, 0.f, 0.f);                                \
        pa1 = make_float4(0.f, 0.f, 0.f, 0.f);                                \
        if (gr0 < NN) pa0 = *(const float4*)(A + (size_t)gr0 * K + (K0) + ac);\
        if (gr1 < NN) pa1 = *(const float4*)(A + (size_t)gr1 * K + (K0) + ac);\
        pb0 = *(const float4*)(B + (size_t)((K0) + br0) * FF + col0 + bc);    \
        pb1 = *(const float4*)(B + (size_t)((K0) + br0 + 8) * FF + col0 + bc);\
    }

#define R2S(BUF)                                                              \
    {                                                                         \
        float2 d;                                                             \
        d.x = d.y = pa0.x; *(float2*)&As[BUF][ac + 0][2 * ar0] = d;           \
        d.x = d.y = pa0.y; *(float2*)&As[BUF][ac + 1][2 * ar0] = d;           \
        d.x = d.y = pa0.z; *(float2*)&As[BUF][ac + 2][2 * ar0] = d;           \
        d.x = d.y = pa0.w; *(float2*)&As[BUF][ac + 3][2 * ar0] = d;           \
        d.x = d.y = pa1.x; *(float2*)&As[BUF][ac + 0][2 * (ar0 + 64)] = d;    \
        d.x = d.y = pa1.y; *(float2*)&As[BUF][ac + 1][2 * (ar0 + 64)] = d;    \
        d.x = d.y = pa1.z; *(float2*)&As[BUF][ac + 2][2 * (ar0 + 64)] = d;    \
        d.x = d.y = pa1.w; *(float2*)&As[BUF][ac + 3][2 * (ar0 + 64)] = d;    \
        *(float4*)&Bs[BUF][br0][bc] = pb0;                                    \
        *(float4*)&Bs[BUF][br0 + 8][bc] = pb1;                                \
    }

    G2R(0);
    R2S(0);
    __syncthreads();

    for (int kb = 0; kb < nk; kb++) {
        int nxt = kb + 1;
        if (nxt < nk) G2R(nxt * 16);
        int buf = kb & 1;
#pragma unroll
        for (int k = 0; k < 16; k++) {
            unsigned long long a2[8], b2[4];
#pragma unroll
            for (int j = 0; j < 4; j++)
                b2[j] = *(const unsigned long long*)&Bs[buf][k][tx * 8 + j * 2];
#pragma unroll
            for (int i = 0; i < 8; i++)
                a2[i] = *(const unsigned long long*)&As[buf][k][(ty * 8 + i) * 2];
#pragma unroll
            for (int i = 0; i < 8; i++)
#pragma unroll
                for (int j = 0; j < 4; j++)
                    asm("fma.rn.f32x2 %0, %1, %2, %0;"
                        : "+l"(acc[i][j]) : "l"(a2[i]), "l"(b2[j]));
        }
        if (nxt < nk) {
            R2S(nxt & 1);
            __syncthreads();
        }
    }
#undef G2R
#undef R2S

    // epilogue: store C (src side only) + fused per-head attention dot
    float av[8];
#pragma unroll
    for (int jj = 0; jj < 8; jj++) av[jj] = att[col0 + tx * 8 + jj];

    int head = (col0 >> 5) + (tx >> 2);

#pragma unroll
    for (int i = 0; i < 8; i++) {
        int gr = row0 + ty * 8 + i;
        float o[8];
#pragma unroll
        for (int j = 0; j < 4; j++)
            asm("mov.b64 {%0, %1}, %2;"
                : "=f"(o[2 * j]), "=f"(o[2 * j + 1]) : "l"(acc[i][j]));
        if (C && gr < NN) {
            float* cp = C + (size_t)gr * FF + col0 + tx * 8;
            *(float4*)cp = make_float4(o[0], o[1], o[2], o[3]);
            *(float4*)(cp + 4) = make_float4(o[4], o[5], o[6], o[7]);
        }
        float p = 0.f;
#pragma unroll
        for (int jj = 0; jj < 8; jj++) p = fmaf(o[jj], av[jj], p);
        p += __shfl_xor_sync(0xffffffffu, p, 1);
        p += __shfl_xor_sync(0xffffffffu, p, 2);
        if ((tx & 3) == 0 && gr < NN) eo[(size_t)gr * HH + head] = p;
    }
}

// ---------------- warp-per-dst segment softmax + aggregation + LN/ReLU ----------------
// POOL=false: write x1[t]; POOL=true: write normalized alpha + mean-pool into g_pooled
template <bool POOL>
__global__ __launch_bounds__(256) void k_edge(const int* __restrict__ ei,
                                              const float* __restrict__ bias_b,
                                              const float* __restrict__ gamma_b,
                                              const float* __restrict__ beta_b,
                                              float* __restrict__ alpha_b,
                                              int alpha_ok) {
    int t = blockIdx.y;
    const int* src = ei + (size_t)t * 2 * NE;
    const float* bias = bias_b + t * FF;
    const float* gamma = gamma_b + t * FF;
    const float* beta = beta_b + t * FF;
    float* alpha = alpha_ok ? (alpha_b + (size_t)t * NE * HH) : g_alpha_fb;
    const float* es = g_es + (size_t)t * NN * HH;
    const float* hs = g_hs + (size_t)t * NN * FF;
    const int* eid = g_eid[t];
    const int* rowp = g_row[t];

    __shared__ float pool_acc[FF];
    if (POOL) {
        pool_acc[threadIdx.x] = 0.0f;
        __syncthreads();
    }

    int d = (blockIdx.x * blockDim.x + threadIdx.x) >> 5;  // exactly NN warps
    int lane = threadIdx.x & 31;
    int h = lane & 7;

    int r0 = rowp[d], r1 = rowp[d + 1];
    float edv = g_ed[(size_t)t * NN * HH + (size_t)d * HH + h];

    // pass 1: per-head max
    float m = -3.0e38f;
    for (int j = r0; j < r1; j++) {
        int s = src[eid[j]];
        float v = es[(size_t)s * HH + h] + edv;
        v = (v > 0.f) ? v : 0.2f * v;
        m = fmaxf(m, v);
    }
    // pass 2: exp-sum (recompute, no scratch stores)
    float den = 0.f;
    for (int j = r0; j < r1; j++) {
        int s = src[eid[j]];
        float v = es[(size_t)s * HH + h] + edv;
        v = (v > 0.f) ? v : 0.2f * v;
        den += __expf(v - m);
    }
    float inv = 1.0f / (den + 1e-16f);

    // pass 3: alpha (recomputed), gather hs[src], accumulate
    float acc[HH];
#pragma unroll
    for (int k = 0; k < HH; k++) acc[k] = 0.f;

    for (int j = r0; j < r1; j++) {
        int e = eid[j];
        int s = src[e];
        float v = es[(size_t)s * HH + h] + edv;
        v = (v > 0.f) ? v : 0.2f * v;
        float a_h = __expf(v - m) * inv;
        if (POOL && lane < 8) alpha[(size_t)e * HH + h] = a_h;
        const float* hsp = hs + (size_t)s * FF + lane;
#pragma unroll
        for (int k = 0; k < HH; k++) {
            float ak = __shfl_sync(0xffffffffu, a_h, k);
            acc[k] = fmaf(ak, hsp[k * CC], acc[k]);
        }
    }

    // epilogue: +bias, LayerNorm over 256 (warp-held), ReLU
    float y[HH];
    float s1 = 0.f, s2 = 0.f;
#pragma unroll
    for (int k = 0; k < HH; k++) {
        float x = acc[k] + bias[k * CC + lane];
        y[k] = x;
        s1 += x;
        s2 = fmaf(x, x, s2);
    }
#pragma unroll
    for (int off = 16; off > 0; off >>= 1) {
        s1 += __shfl_xor_sync(0xffffffffu, s1, off);
        s2 += __shfl_xor_sync(0xffffffffu, s2, off);
    }
    float mu = s1 * (1.0f / FF);
    float var = s2 * (1.0f / FF) - mu * mu;
    float rstd = rsqrtf(var + 1e-5f);
#pragma unroll
    for (int k = 0; k < HH; k++) {
        int c = k * CC + lane;
        float v = fmaf((y[k] - mu) * rstd, gamma[c], beta[c]);
        v = fmaxf(v, 0.0f);
        if (POOL) atomicAdd(&pool_acc[c], v);
        else g_x1[(size_t)t * NN * FF + (size_t)d * FF + c] = v;
    }

    if (POOL) {
        __syncthreads();
        atomicAdd(&g_pooled[t * FF + threadIdx.x], pool_acc[threadIdx.x] * (1.0f / NN));
    }
}

// ---------------- final classifier dot ----------------
__global__ void k_final(const float* __restrict__ Wc, const float* __restrict__ bc,
                        float* __restrict__ out) {
    __shared__ float sm[256];
    int tid = threadIdx.x;
    float s = 0.f;
    for (int i = tid; i < NT * FF + DI; i += 256) s = fmaf(g_pooled[i], Wc[i], s);
    sm[tid] = s;
    __syncthreads();
    for (int off = 128; off > 0; off >>= 1) {
        if (tid < off) sm[tid] += sm[tid + off];
        __syncthreads();
    }
    if (tid == 0) out[0] = sm[0] + bc[0];
}

// ---------------- launch ----------------
extern "C" void kernel_launch(void* const* d_in, const int* in_sizes, int n_in,
                              void* d_out, int out_size) {
    const float* x_pkg = (const float*)d_in[0];
    const float* x_tgt = (const float*)d_in[1];
    const int*   ei    = (const int*)d_in[2];
    const float* W1s   = (const float*)d_in[3];
    const float* W1d   = (const float*)d_in[4];
    const float* a1s   = (const float*)d_in[5];
    const float* a1d   = (const float*)d_in[6];
    const float* b1    = (const float*)d_in[7];
    const float* W2s   = (const float*)d_in[8];
    const float* W2d   = (const float*)d_in[9];
    const float* a2s   = (const float*)d_in[10];
    const float* a2d   = (const float*)d_in[11];
    const float* b2    = (const float*)d_in[12];
    const float* gamma = (const float*)d_in[13];
    const float* beta  = (const float*)d_in[14];
    const float* Wc    = (const float*)d_in[15];
    const float* bc    = (const float*)d_in[16];
    float* out = (float*)d_out;

    const int alpha_ok = (out_size >= 1 + NT * NE * HH) ? 1 : 0;

    k_zero_pooled<<<7, 256>>>();
    k_pkg_mean<<<100, 128>>>(x_pkg);

    // CSR for all 6 types
    k_zero_cnt<<<(NT * NN + 255) / 256, 256>>>();
    dim3 gh(391, NT);
    k_hist<<<gh, 256>>>(ei);
    k_scan<<<NT, 1024>>>();
    k_scatter<<<gh, 256>>>(ei);

    dim3 gg(235, 2, 2 * NT);
    dim3 ge(3750, NT);

    // layer 1: all 12 GEMMs in one launch (es/ed fused into epilogue)
    k_gemm<<<gg, 256>>>(x_pkg, x_tgt, W1s, W1d, a1s, a1d, DI);
    k_edge<false><<<ge, 256>>>(ei, b1, gamma, beta, out + 1, alpha_ok);

    // layer 2 (dst A = g_x1, K=256)
    k_gemm<<<gg, 256>>>(x_pkg, nullptr, W2s, W2d, a2s, a2d, FF);
    k_edge<true><<<ge, 256>>>(ei, b2, gamma, beta, out + 1, alpha_ok);

    k_final<<<1, 256>>>(Wc, bc, out);
}